// round 11
// baseline (speedup 1.0000x reference)
#include <cuda_runtime.h>
#include <cuda_bf16.h>

#define NE 100000
#define NN 10000
#define PI_F 3.14159265358979323846f
#define SQRT_2_CUT 0.6030226891555273f
#define CAP 192                 // edges per smem chunk (192*128B = 24KB)

// g_cnt packed: low 16 = total degree, high 16 = z=1 count. Statically zero-init;
// gather re-zeroes after reading.
__device__ int g_cnt[NN];
__device__ int g_start[NN];
__device__ int g_cur_lo[NN];    // z=0 cursor (counts up from start)
__device__ int g_cur_hi[NN];    // z=1 cursor (counts down from start+tot-1)
// Payload per CSR slot: 32 floats (one 128B line):
// [0:20)=mon_a*sc, [20:28)=sin(n*theta), [28:32)=pad
__device__ __align__(128) float g_pay[NE * 32];

__global__ void __launch_bounds__(256) hist_kernel(const int* __restrict__ ei,
                                                   const int* __restrict__ an) {
    int e = blockIdx.x * blockDim.x + threadIdx.x;
    if (e < NE) {
        int z = an[ei[e]];
        atomicAdd(&g_cnt[ei[NE + e]], 1 | (z << 16));
    }
}

// Single block, 1024 threads, coalesced smem-staged scan over (cnt & 0xffff)
__global__ void __launch_bounds__(1024) scan_kernel() {
    __shared__ int sh[10240];
    __shared__ int wsum[32];
    int tid = threadIdx.x;

    for (int i = tid; i < 10240; i += 1024) sh[i] = (i < NN) ? (g_cnt[i] & 0xffff) : 0;
    __syncthreads();

    int base = tid * 10;
    int local[10];
    int sum = 0;
#pragma unroll
    for (int k = 0; k < 10; k++) { local[k] = sum; sum += sh[base + k]; }

    int lane = tid & 31, w = tid >> 5;
    int incl = sum;
#pragma unroll
    for (int d = 1; d < 32; d <<= 1) {
        int v = __shfl_up_sync(0xffffffffu, incl, d);
        if (lane >= d) incl += v;
    }
    if (lane == 31) wsum[w] = incl;
    __syncthreads();
    if (w == 0) {
        int v = wsum[lane];
        int inc2 = v;
#pragma unroll
        for (int d = 1; d < 32; d <<= 1) {
            int t2 = __shfl_up_sync(0xffffffffu, inc2, d);
            if (lane >= d) inc2 += t2;
        }
        wsum[lane] = inc2 - v;
    }
    __syncthreads();

    int excl = incl - sum + wsum[w];
    // need tot again to place hi cursor; recompute from scan: store excl, then fix up
#pragma unroll
    for (int k = 0; k < 10; k++) {
        int idx = base + k;
        if (idx < NN) {
            int st  = excl + local[k];
            int tot = g_cnt[idx] & 0xffff;
            g_start[idx]  = st;
            g_cur_lo[idx] = st;
            g_cur_hi[idx] = st + tot - 1;
        }
    }
}

// scatter: per-edge math, payload into CSR slot; z=0 forward, z=1 backward
__global__ void __launch_bounds__(256) scatter_kernel(const int* __restrict__ ei,
                                                      const int* __restrict__ an,
                                                      const float* __restrict__ el,
                                                      const float* __restrict__ ev) {
    int e = blockIdx.x * blockDim.x + threadIdx.x;
    if (e >= NE) return;

    int src = ei[e];
    int dst = ei[NE + e];
    int z   = an[src];
    float r  = el[e];
    float vx = ev[3 * e + 0];
    float vy = ev[3 * e + 1];
    float vz = ev[3 * e + 2];

    float inv = rsqrtf(vx * vx + vy * vy + vz * vz);
    float x = vx * inv, y = vy * inv, zc = vz * inv;

    float u  = r * (1.0f / 5.5f);
    float u2 = u * u;
    float u6 = u2 * u2 * u2;
    float fc = 1.0f - 28.0f * u6 + 48.0f * u6 * u - 21.0f * u6 * u2;
    fc = (u < 1.0f) ? fc : 0.0f;

    float s, c;
    sincosf(PI_F * u, &s, &c);
    float sc   = SQRT_2_CUT / r * fc;
    float twoc = 2.0f * c;

    // monomials * sc
    float a0 = sc;
    float a1 = x * sc,  a2 = y * sc,  a3 = zc * sc;
    float a4 = x * a1,  a5 = y * a1,  a6 = zc * a1;
    float a7 = y * a2,  a8 = zc * a2, a9 = zc * a3;
    float a10 = x * a4, a11 = y * a4, a12 = zc * a4;
    float a13 = y * a5, a14 = zc * a5, a15 = zc * a6;
    float a16 = y * a7, a17 = zc * a7, a18 = zc * a8, a19 = zc * a9;

    // sin(n*theta), n=1..8 via Chebyshev
    float s1 = s;
    float s2 = twoc * s1;
    float s3 = fmaf(twoc, s2, -s1);
    float s4 = fmaf(twoc, s3, -s2);
    float s5 = fmaf(twoc, s4, -s3);
    float s6 = fmaf(twoc, s5, -s4);
    float s7 = fmaf(twoc, s6, -s5);
    float s8 = fmaf(twoc, s7, -s6);

    int pos = z ? atomicSub(&g_cur_hi[dst], 1) : atomicAdd(&g_cur_lo[dst], 1);
    float4* P = reinterpret_cast<float4*>(g_pay + (size_t)pos * 32);
    P[0] = make_float4(a0,  a1,  a2,  a3);
    P[1] = make_float4(a4,  a5,  a6,  a7);
    P[2] = make_float4(a8,  a9,  a10, a11);
    P[3] = make_float4(a12, a13, a14, a15);
    P[4] = make_float4(a16, a17, a18, a19);
    P[5] = make_float4(s1, s2, s3, s4);
    P[6] = make_float4(s5, s6, s7, s8);
    P[7] = make_float4(0.0f, 0.0f, 0.0f, 0.0f);
}

// Block of 256 = 8 warps handles 8 consecutive nodes (contiguous CSR range).
// Payload staged through smem; species-split sub-loops with single accumulator set.
__global__ void __launch_bounds__(256, 6) gather_kernel(const int* __restrict__ an,
                                                        const float* __restrict__ W,
                                                        float* __restrict__ out) {
    __shared__ float pay_sh[CAP * 32];    // 24KB; reused as transpose buffer post-loop
    __shared__ int   sh_hi;
    int tid    = threadIdx.x;
    int lane   = tid & 31;
    int warpid = tid >> 5;
    int node   = blockIdx.x * 8 + warpid;        // 1250 blocks * 8 = 10000
    int node0  = blockIdx.x * 8;

    int pk    = g_cnt[node];
    int n_tot = pk & 0xffff;
    int n_z1  = pk >> 16;
    if (lane == 0) g_cnt[node] = 0;              // restore zero state for next replay
    int s0 = g_start[node];
    int m  = s0 + n_tot - n_z1;                  // z-species boundary
    int s1 = s0 + n_tot;

    int blk_lo = g_start[node0];
    if (warpid == 7 && lane == 0) sh_hi = s1;

    float accA[8], accB[8];                      // S0 (z=0), S1 (z=1)
#pragma unroll
    for (int n = 0; n < 8; n++) { accA[n] = 0.0f; accB[n] = 0.0f; }

    __syncthreads();
    int blk_hi = sh_hi;

    for (int lo = blk_lo; lo < blk_hi; lo += CAP) {
        int cnt = min(CAP, blk_hi - lo);
        int hi  = lo + cnt;
        // cooperative load: cnt*8 float4s, coalesced
        const float4* src4 = reinterpret_cast<const float4*>(g_pay + (size_t)lo * 32);
        int n4 = cnt * 8;
        for (int i = tid; i < n4; i += 256)
            reinterpret_cast<float4*>(pay_sh)[i] = src4[i];
        __syncthreads();

        // z=0 sub-segment within chunk
        int a0i = max(s0, lo), b0i = min(m, hi);
#pragma unroll 2
        for (int t = a0i; t < b0i; t++) {
            const float* P = pay_sh + (t - lo) * 32;
            float  mA = P[lane];
            float4 qa = *reinterpret_cast<const float4*>(P + 20);
            float4 qb = *reinterpret_cast<const float4*>(P + 24);
            accA[0] = fmaf(mA, qa.x, accA[0]);
            accA[1] = fmaf(mA, qa.y, accA[1]);
            accA[2] = fmaf(mA, qa.z, accA[2]);
            accA[3] = fmaf(mA, qa.w, accA[3]);
            accA[4] = fmaf(mA, qb.x, accA[4]);
            accA[5] = fmaf(mA, qb.y, accA[5]);
            accA[6] = fmaf(mA, qb.z, accA[6]);
            accA[7] = fmaf(mA, qb.w, accA[7]);
        }
        // z=1 sub-segment within chunk
        int a1i = max(m, lo), b1i = min(s1, hi);
#pragma unroll 2
        for (int t = a1i; t < b1i; t++) {
            const float* P = pay_sh + (t - lo) * 32;
            float  mB = P[lane];
            float4 qa = *reinterpret_cast<const float4*>(P + 20);
            float4 qb = *reinterpret_cast<const float4*>(P + 24);
            accB[0] = fmaf(mB, qa.x, accB[0]);
            accB[1] = fmaf(mB, qa.y, accB[1]);
            accB[2] = fmaf(mB, qa.z, accB[2]);
            accB[3] = fmaf(mB, qa.w, accB[3]);
            accB[4] = fmaf(mB, qb.x, accB[4]);
            accB[5] = fmaf(mB, qb.y, accB[5]);
            accB[6] = fmaf(mB, qb.z, accB[6]);
            accB[7] = fmaf(mB, qb.w, accB[7]);
        }
        __syncthreads();   // chunk fully consumed before overwrite / transpose reuse
    }

    // Transpose through (reused) shared: [z][r][a]
    float* sw = pay_sh + warpid * 320;
    if (lane < 20) {
#pragma unroll
        for (int n = 0; n < 8; n++) {
            sw[n * 20 + lane]       = accA[n];
            sw[160 + n * 20 + lane] = accB[n];
        }
    }
    __syncwarp();

    // r-major epilogue: lane -> (r = lane/4, g = lane%4 owning a = 5g..5g+4)
    int r = lane >> 2;
    int g = lane & 3;
    const float* p0 = sw + r * 20 + g * 5;
    const float* p1 = p0 + 160;

    float W00 = W[0], W01 = W[1], W02 = W[2];
    float W10 = W[3], W11 = W[4], W12 = W[5];

    float C[5][3];
#pragma unroll
    for (int k = 0; k < 5; k++) {
        float v0 = p0[k], v1 = p1[k];
        C[k][0] = fmaf(v0, W00, v1 * W10);
        C[k][1] = fmaf(v0, W01, v1 * W11);
        C[k][2] = fmaf(v0, W02, v1 * W12);
    }

    float D0[3] = {0, 0, 0}, D1[3] = {0, 0, 0}, D2[3] = {0, 0, 0}, D3[3] = {0, 0, 0};
    if (g == 0) {
#pragma unroll
        for (int i = 0; i < 3; i++) {
            D0[i] = C[0][i];
            D1[i] = C[1][i] * C[1][i] + C[2][i] * C[2][i] + C[3][i] * C[3][i];
            D2[i] = C[4][i] * C[4][i];
        }
    } else if (g == 1) {
#pragma unroll
        for (int i = 0; i < 3; i++)
            D2[i] = 2.0f * C[0][i] * C[0][i] + 2.0f * C[1][i] * C[1][i] + C[2][i] * C[2][i]
                  + 2.0f * C[3][i] * C[3][i] + C[4][i] * C[4][i];
    } else if (g == 2) {
#pragma unroll
        for (int i = 0; i < 3; i++)
            D3[i] = C[0][i] * C[0][i] + 3.0f * C[1][i] * C[1][i] + 3.0f * C[2][i] * C[2][i]
                  + 3.0f * C[3][i] * C[3][i] + 6.0f * C[4][i] * C[4][i];
    } else {
#pragma unroll
        for (int i = 0; i < 3; i++)
            D3[i] = 3.0f * C[0][i] * C[0][i] + C[1][i] * C[1][i] + 3.0f * C[2][i] * C[2][i]
                  + 3.0f * C[3][i] * C[3][i] + C[4][i] * C[4][i];
    }

#pragma unroll
    for (int msk = 1; msk <= 2; msk <<= 1) {
#pragma unroll
        for (int i = 0; i < 3; i++) {
            D0[i] += __shfl_xor_sync(0xffffffffu, D0[i], msk);
            D1[i] += __shfl_xor_sync(0xffffffffu, D1[i], msk);
            D2[i] += __shfl_xor_sync(0xffffffffu, D2[i], msk);
            D3[i] += __shfl_xor_sync(0xffffffffu, D3[i], msk);
        }
    }

    if (g == 0) {
        int   zn = an[node];
        float e0 = zn ? W10 : W00;
        float e1 = zn ? W11 : W01;
        float e2 = zn ? W12 : W02;
        float q0 = e0 * e0, q1 = e1 * e1, q2 = e2 * e2;

        float v[36];
        v[0] = D0[0] * e0;  v[1] = D0[0] * e1;  v[2] = D0[0] * e2;
        v[3] = D0[1] * e0;  v[4] = D0[1] * e1;  v[5] = D0[1] * e2;
        v[6] = D0[2] * e0;  v[7] = D0[2] * e1;  v[8] = D0[2] * e2;

        v[9]  = D1[0] * q0; v[10] = D1[0] * q1; v[11] = D1[0] * q2;
        v[12] = D1[1] * q0; v[13] = D1[1] * q1; v[14] = D1[1] * q2;
        v[15] = D1[2] * q0; v[16] = D1[2] * q1; v[17] = D1[2] * q2;

        v[18] = D2[0] * q0; v[19] = D2[0] * q1; v[20] = D2[0] * q2;
        v[21] = D2[1] * q0; v[22] = D2[1] * q1; v[23] = D2[1] * q2;
        v[24] = D2[2] * q0; v[25] = D2[2] * q1; v[26] = D2[2] * q2;

        v[27] = D3[0] * q0; v[28] = D3[0] * q1; v[29] = D3[0] * q2;
        v[30] = D3[1] * q0; v[31] = D3[1] * q1; v[32] = D3[1] * q2;
        v[33] = D3[2] * q0; v[34] = D3[2] * q1; v[35] = D3[2] * q2;

        float4* o = reinterpret_cast<float4*>(out + (size_t)(node * 8 + r) * 36);
#pragma unroll
        for (int k = 0; k < 9; k++)
            o[k] = make_float4(v[4 * k], v[4 * k + 1], v[4 * k + 2], v[4 * k + 3]);
    }
}

extern "C" void kernel_launch(void* const* d_in, const int* in_sizes, int n_in,
                              void* d_out, int out_size) {
    const int*   an = (const int*)d_in[1];
    const int*   ei = (const int*)d_in[2];
    const float* el = (const float*)d_in[3];
    const float* ev = (const float*)d_in[4];
    const float* W  = (const float*)d_in[5];
    float* out = (float*)d_out;

    hist_kernel<<<(NE + 255) / 256, 256>>>(ei, an);
    scan_kernel<<<1, 1024>>>();
    scatter_kernel<<<(NE + 255) / 256, 256>>>(ei, an, el, ev);
    gather_kernel<<<1250, 256>>>(an, W, out);   // 8 nodes per block
}

// round 12
// speedup vs baseline: 1.1241x; 1.1241x over previous
#include <cuda_runtime.h>
#include <cuda_bf16.h>

#define NE 100000
#define NN 10000
#define PI_F 3.14159265358979323846f
#define SQRT_2_CUT 0.6030226891555273f
#define CAP 192                 // edges per smem chunk (192*128B = 24KB)

__device__ int g_cnt[NN];      // statically zero-init; gather re-zeroes after reading
__device__ int g_start[NN];
__device__ int g_cursor[NN];
// Payload per CSR slot: 32 floats (one 128B line):
// [0:20)=mon_a*sc, [20]=sign word, [21:24)=pad, [24:32)=sin(n*theta)
__device__ __align__(128) float g_pay[NE * 32];
// Accumulated sums: [node][ S(8x20) | D(8x20) ]  (320 floats per node)
__device__ __align__(16) float g_S[NN * 320];

__constant__ int   c_lvl[20]  = {0, 1,1,1, 2,2,2,2,2,2, 3,3,3,3,3,3,3,3,3,3};
__constant__ float c_pref[20] = {1.f, 1.f,1.f,1.f,
                                 1.f,2.f,2.f,1.f,2.f,1.f,
                                 1.f,3.f,3.f,3.f,6.f,3.f,1.f,3.f,3.f,1.f};

__global__ void __launch_bounds__(256) hist_kernel(const int* __restrict__ ei) {
    int e = blockIdx.x * blockDim.x + threadIdx.x;
    if (e < NE) atomicAdd(&g_cnt[ei[NE + e]], 1);
}

// Single block, 1024 threads, coalesced smem-staged scan
__global__ void __launch_bounds__(1024) scan_kernel() {
    __shared__ int sh[10240];
    __shared__ int wsum[32];
    int tid = threadIdx.x;

    for (int i = tid; i < 10240; i += 1024) sh[i] = (i < NN) ? g_cnt[i] : 0;
    __syncthreads();

    int base = tid * 10;
    int local[10];
    int sum = 0;
#pragma unroll
    for (int k = 0; k < 10; k++) { local[k] = sum; sum += sh[base + k]; }

    int lane = tid & 31, w = tid >> 5;
    int incl = sum;
#pragma unroll
    for (int d = 1; d < 32; d <<= 1) {
        int v = __shfl_up_sync(0xffffffffu, incl, d);
        if (lane >= d) incl += v;
    }
    if (lane == 31) wsum[w] = incl;
    __syncthreads();
    if (w == 0) {
        int v = wsum[lane];
        int inc2 = v;
#pragma unroll
        for (int d = 1; d < 32; d <<= 1) {
            int t2 = __shfl_up_sync(0xffffffffu, inc2, d);
            if (lane >= d) inc2 += t2;
        }
        wsum[lane] = inc2 - v;
    }
    __syncthreads();

    int excl = incl - sum + wsum[w];
#pragma unroll
    for (int k = 0; k < 10; k++) sh[base + k] = excl + local[k];
    __syncthreads();

    for (int i = tid; i < NN; i += 1024) {
        int v = sh[i];
        g_start[i]  = v;
        g_cursor[i] = v;
    }
}

// scatter: per-edge math, payload written directly into CSR slot (one 128B line)
__global__ void __launch_bounds__(256) scatter_kernel(const int* __restrict__ ei,
                                                      const int* __restrict__ an,
                                                      const float* __restrict__ el,
                                                      const float* __restrict__ ev) {
    int e = blockIdx.x * blockDim.x + threadIdx.x;
    if (e >= NE) return;

    int src = ei[e];
    int dst = ei[NE + e];
    int z   = an[src];
    float r  = el[e];
    float vx = ev[3 * e + 0];
    float vy = ev[3 * e + 1];
    float vz = ev[3 * e + 2];

    float inv = rsqrtf(vx * vx + vy * vy + vz * vz);
    float x = vx * inv, y = vy * inv, zc = vz * inv;

    float u  = r * (1.0f / 5.5f);
    float u2 = u * u;
    float u6 = u2 * u2 * u2;
    float fc = 1.0f - 28.0f * u6 + 48.0f * u6 * u - 21.0f * u6 * u2;
    fc = (u < 1.0f) ? fc : 0.0f;

    float s, c;
    sincosf(PI_F * u, &s, &c);
    float sc   = SQRT_2_CUT / r * fc;          // positive
    float twoc = 2.0f * c;

    // monomials * sc
    float a0 = sc;
    float a1 = x * sc,  a2 = y * sc,  a3 = zc * sc;
    float a4 = x * a1,  a5 = y * a1,  a6 = zc * a1;
    float a7 = y * a2,  a8 = zc * a2, a9 = zc * a3;
    float a10 = x * a4, a11 = y * a4, a12 = zc * a4;
    float a13 = y * a5, a14 = zc * a5, a15 = zc * a6;
    float a16 = y * a7, a17 = zc * a7, a18 = zc * a8, a19 = zc * a9;

    // sin(n*theta), n=1..8 via Chebyshev
    float s1 = s;
    float s2 = twoc * s1;
    float s3 = fmaf(twoc, s2, -s1);
    float s4 = fmaf(twoc, s3, -s2);
    float s5 = fmaf(twoc, s4, -s3);
    float s6 = fmaf(twoc, s5, -s4);
    float s7 = fmaf(twoc, s6, -s5);
    float s8 = fmaf(twoc, s7, -s6);

    float sgn = __uint_as_float(z ? 0x80000000u : 0u);

    int pos = atomicAdd(&g_cursor[dst], 1);
    float4* P = reinterpret_cast<float4*>(g_pay + (size_t)pos * 32);
    P[0] = make_float4(a0,  a1,  a2,  a3);
    P[1] = make_float4(a4,  a5,  a6,  a7);
    P[2] = make_float4(a8,  a9,  a10, a11);
    P[3] = make_float4(a12, a13, a14, a15);
    P[4] = make_float4(a16, a17, a18, a19);
    P[5] = make_float4(sgn, 0.0f, 0.0f, 0.0f);
    P[6] = make_float4(s1, s2, s3, s4);
    P[7] = make_float4(s5, s6, s7, s8);
}

// Accumulate-only gather: 8 warps = 8 consecutive nodes; smem-staged chunks;
// results written raw (S, D) to g_S. No epilogue here.
__global__ void __launch_bounds__(256, 8) gather_kernel(float* __restrict__ dummy) {
    __shared__ float pay_sh[CAP * 32];    // 24KB
    __shared__ int   sh_hi;
    int tid    = threadIdx.x;
    int lane   = tid & 31;
    int warpid = tid >> 5;
    int node   = blockIdx.x * 8 + warpid;        // 1250 blocks * 8 = 10000
    int node0  = blockIdx.x * 8;

    int s0  = g_start[node];
    int n_e = g_cnt[node];
    if (lane == 0) g_cnt[node] = 0;              // restore zero state for next replay
    int s1  = s0 + n_e;

    int blk_lo = g_start[node0];
    if (warpid == 7 && lane == 0) sh_hi = s1;

    float accS[8], accD[8];
#pragma unroll
    for (int n = 0; n < 8; n++) { accS[n] = 0.0f; accD[n] = 0.0f; }

    __syncthreads();
    int blk_hi = sh_hi;

    for (int lo = blk_lo; lo < blk_hi; lo += CAP) {
        int cnt = min(CAP, blk_hi - lo);
        const float4* src4 = reinterpret_cast<const float4*>(g_pay + (size_t)lo * 32);
        int n4 = cnt * 8;
        for (int i = tid; i < n4; i += 256)
            reinterpret_cast<float4*>(pay_sh)[i] = src4[i];
        __syncthreads();

        int a = max(s0, lo);
        int b = min(s1, lo + cnt);
#pragma unroll 2
        for (int t = a; t < b; t++) {
            const float* P = pay_sh + (t - lo) * 32;
            float  mA  = P[lane];                                // lanes 0..19 meaningful
            float4 qa  = *reinterpret_cast<const float4*>(P + 24);
            float4 qb  = *reinterpret_cast<const float4*>(P + 28);
            unsigned sgn = __float_as_uint(P[20]);
            float  mS  = __uint_as_float(__float_as_uint(mA) ^ sgn);

            accS[0] = fmaf(mA, qa.x, accS[0]);  accD[0] = fmaf(mS, qa.x, accD[0]);
            accS[1] = fmaf(mA, qa.y, accS[1]);  accD[1] = fmaf(mS, qa.y, accD[1]);
            accS[2] = fmaf(mA, qa.z, accS[2]);  accD[2] = fmaf(mS, qa.z, accD[2]);
            accS[3] = fmaf(mA, qa.w, accS[3]);  accD[3] = fmaf(mS, qa.w, accD[3]);
            accS[4] = fmaf(mA, qb.x, accS[4]);  accD[4] = fmaf(mS, qb.x, accD[4]);
            accS[5] = fmaf(mA, qb.y, accS[5]);  accD[5] = fmaf(mS, qb.y, accD[5]);
            accS[6] = fmaf(mA, qb.z, accS[6]);  accD[6] = fmaf(mS, qb.z, accD[6]);
            accS[7] = fmaf(mA, qb.w, accS[7]);  accD[7] = fmaf(mS, qb.w, accD[7]);
        }
        __syncthreads();
    }

    // Raw store: S then D, per (n, a) slot. Lanes 20+ idle.
    if (lane < 20) {
        float* pS = g_S + (size_t)node * 320 + lane;
#pragma unroll
        for (int n = 0; n < 8; n++) {
            pS[n * 20]       = accS[n];
            pS[160 + n * 20] = accD[n];
        }
    }
}

// Thread-parallel epilogue: one thread per (node, rbf). C = S*U0 + D*U1 with
// U0 = (W0+W1)/2, U1 = (W0-W1)/2 (folds the sum/diff reconstruction into weights).
__global__ void __launch_bounds__(256) epi_kernel(const int* __restrict__ an,
                                                  const float* __restrict__ W,
                                                  float* __restrict__ out) {
    int t = blockIdx.x * blockDim.x + threadIdx.x;
    if (t >= NN * 8) return;
    int node = t >> 3;
    int r    = t & 7;

    float W00 = W[0], W01 = W[1], W02 = W[2];
    float W10 = W[3], W11 = W[4], W12 = W[5];
    float U00 = 0.5f * (W00 + W10), U01 = 0.5f * (W01 + W11), U02 = 0.5f * (W02 + W12);
    float U10 = 0.5f * (W00 - W10), U11 = 0.5f * (W01 - W11), U12 = 0.5f * (W02 - W12);

    const float* pS = g_S + (size_t)node * 320 + r * 20;
    const float* pD = pS + 160;

    float D0[3] = {0, 0, 0}, DL[3][3] = {{0,0,0},{0,0,0},{0,0,0}};
#pragma unroll
    for (int a = 0; a < 20; a++) {
        float S = pS[a];
        float D = pD[a];
        float C0 = fmaf(S, U00, D * U10);
        float C1 = fmaf(S, U01, D * U11);
        float C2 = fmaf(S, U02, D * U12);
        if (a == 0) {
            D0[0] = C0; D0[1] = C1; D0[2] = C2;
        } else {
            int   l = c_lvl[a] - 1;
            float p = c_pref[a];
            DL[l][0] = fmaf(p * C0, C0, DL[l][0]);
            DL[l][1] = fmaf(p * C1, C1, DL[l][1]);
            DL[l][2] = fmaf(p * C2, C2, DL[l][2]);
        }
    }

    int   zn = an[node];
    float e0 = zn ? W10 : W00;
    float e1 = zn ? W11 : W01;
    float e2 = zn ? W12 : W02;
    float q0 = e0 * e0, q1 = e1 * e1, q2 = e2 * e2;

    float v[36];
    v[0] = D0[0] * e0;  v[1] = D0[0] * e1;  v[2] = D0[0] * e2;
    v[3] = D0[1] * e0;  v[4] = D0[1] * e1;  v[5] = D0[1] * e2;
    v[6] = D0[2] * e0;  v[7] = D0[2] * e1;  v[8] = D0[2] * e2;
#pragma unroll
    for (int l = 0; l < 3; l++) {
        float* vf = v + 9 + l * 9;
        vf[0] = DL[l][0] * q0;  vf[1] = DL[l][0] * q1;  vf[2] = DL[l][0] * q2;
        vf[3] = DL[l][1] * q0;  vf[4] = DL[l][1] * q1;  vf[5] = DL[l][1] * q2;
        vf[6] = DL[l][2] * q0;  vf[7] = DL[l][2] * q1;  vf[8] = DL[l][2] * q2;
    }

    float4* o = reinterpret_cast<float4*>(out + (size_t)t * 36);
#pragma unroll
    for (int k = 0; k < 9; k++)
        o[k] = make_float4(v[4 * k], v[4 * k + 1], v[4 * k + 2], v[4 * k + 3]);
}

extern "C" void kernel_launch(void* const* d_in, const int* in_sizes, int n_in,
                              void* d_out, int out_size) {
    const int*   an = (const int*)d_in[1];
    const int*   ei = (const int*)d_in[2];
    const float* el = (const float*)d_in[3];
    const float* ev = (const float*)d_in[4];
    const float* W  = (const float*)d_in[5];
    float* out = (float*)d_out;

    hist_kernel<<<(NE + 255) / 256, 256>>>(ei);
    scan_kernel<<<1, 1024>>>();
    scatter_kernel<<<(NE + 255) / 256, 256>>>(ei, an, el, ev);
    gather_kernel<<<1250, 256>>>(out);               // accumulate-only
    epi_kernel<<<(NN * 8 + 255) / 256, 256>>>(an, W, out);
}

// round 14
// speedup vs baseline: 1.2655x; 1.1258x over previous
#include <cuda_runtime.h>
#include <cuda_bf16.h>

#define NE 100000
#define NN 10000
#define PI_F 3.14159265358979323846f
#define SQRT_2_CUT 0.6030226891555273f
#define CAP 192                 // edges per smem chunk (192*128B = 24KB)

__device__ int g_cnt[NN];      // statically zero-init; gather re-zeroes after reading
__device__ int g_start[NN];
__device__ int g_cursor[NN];
// Payload per CSR slot: 32 floats (one 128B line):
// [0:20)=mon_a*sc, [20]=sign word, [21:24)=pad, [24:32)=sin(n*theta)
__device__ __align__(128) float g_pay[NE * 32];

__global__ void __launch_bounds__(256) hist_kernel(const int* __restrict__ ei) {
    int e = blockIdx.x * blockDim.x + threadIdx.x;
    if (e < NE) atomicAdd(&g_cnt[ei[NE + e]], 1);
}

// Single block, 1024 threads, coalesced smem-staged scan
__global__ void __launch_bounds__(1024) scan_kernel() {
    __shared__ int sh[10240];
    __shared__ int wsum[32];
    int tid = threadIdx.x;

    for (int i = tid; i < 10240; i += 1024) sh[i] = (i < NN) ? g_cnt[i] : 0;
    __syncthreads();

    int base = tid * 10;
    int local[10];
    int sum = 0;
#pragma unroll
    for (int k = 0; k < 10; k++) { local[k] = sum; sum += sh[base + k]; }

    int lane = tid & 31, w = tid >> 5;
    int incl = sum;
#pragma unroll
    for (int d = 1; d < 32; d <<= 1) {
        int v = __shfl_up_sync(0xffffffffu, incl, d);
        if (lane >= d) incl += v;
    }
    if (lane == 31) wsum[w] = incl;
    __syncthreads();
    if (w == 0) {
        int v = wsum[lane];
        int inc2 = v;
#pragma unroll
        for (int d = 1; d < 32; d <<= 1) {
            int t2 = __shfl_up_sync(0xffffffffu, inc2, d);
            if (lane >= d) inc2 += t2;
        }
        wsum[lane] = inc2 - v;
    }
    __syncthreads();

    int excl = incl - sum + wsum[w];
#pragma unroll
    for (int k = 0; k < 10; k++) sh[base + k] = excl + local[k];
    __syncthreads();

    for (int i = tid; i < NN; i += 1024) {
        int v = sh[i];
        g_start[i]  = v;
        g_cursor[i] = v;
    }
}

// scatter: per-edge math, payload written directly into CSR slot (one 128B line)
__global__ void __launch_bounds__(256) scatter_kernel(const int* __restrict__ ei,
                                                      const int* __restrict__ an,
                                                      const float* __restrict__ el,
                                                      const float* __restrict__ ev) {
    int e = blockIdx.x * blockDim.x + threadIdx.x;
    if (e >= NE) return;

    int src = ei[e];
    int dst = ei[NE + e];
    int z   = an[src];
    float r  = el[e];
    float vx = ev[3 * e + 0];
    float vy = ev[3 * e + 1];
    float vz = ev[3 * e + 2];

    float inv = rsqrtf(vx * vx + vy * vy + vz * vz);
    float x = vx * inv, y = vy * inv, zc = vz * inv;

    float u  = r * (1.0f / 5.5f);
    float u2 = u * u;
    float u6 = u2 * u2 * u2;
    float fc = 1.0f - 28.0f * u6 + 48.0f * u6 * u - 21.0f * u6 * u2;
    fc = (u < 1.0f) ? fc : 0.0f;

    float s, c;
    sincosf(PI_F * u, &s, &c);
    float sc   = SQRT_2_CUT / r * fc;          // positive
    float twoc = 2.0f * c;

    // monomials * sc
    float a0 = sc;
    float a1 = x * sc,  a2 = y * sc,  a3 = zc * sc;
    float a4 = x * a1,  a5 = y * a1,  a6 = zc * a1;
    float a7 = y * a2,  a8 = zc * a2, a9 = zc * a3;
    float a10 = x * a4, a11 = y * a4, a12 = zc * a4;
    float a13 = y * a5, a14 = zc * a5, a15 = zc * a6;
    float a16 = y * a7, a17 = zc * a7, a18 = zc * a8, a19 = zc * a9;

    // sin(n*theta), n=1..8 via Chebyshev
    float s1 = s;
    float s2 = twoc * s1;
    float s3 = fmaf(twoc, s2, -s1);
    float s4 = fmaf(twoc, s3, -s2);
    float s5 = fmaf(twoc, s4, -s3);
    float s6 = fmaf(twoc, s5, -s4);
    float s7 = fmaf(twoc, s6, -s5);
    float s8 = fmaf(twoc, s7, -s6);

    float sgn = __uint_as_float(z ? 0x80000000u : 0u);

    int pos = atomicAdd(&g_cursor[dst], 1);
    float4* P = reinterpret_cast<float4*>(g_pay + (size_t)pos * 32);
    P[0] = make_float4(a0,  a1,  a2,  a3);
    P[1] = make_float4(a4,  a5,  a6,  a7);
    P[2] = make_float4(a8,  a9,  a10, a11);
    P[3] = make_float4(a12, a13, a14, a15);
    P[4] = make_float4(a16, a17, a18, a19);
    P[5] = make_float4(sgn, 0.0f, 0.0f, 0.0f);
    P[6] = make_float4(s1, s2, s3, s4);
    P[7] = make_float4(s5, s6, s7, s8);
}

// 2 warps per node (rbf split 4+4); 256-thread block = 4 nodes.
// Smem-staged chunks; in-kernel epilogue by warps 0..3.
__global__ void __launch_bounds__(256) gather_kernel(const int* __restrict__ an,
                                                     const float* __restrict__ W,
                                                     float* __restrict__ out) {
    __shared__ float pay_sh[CAP * 32];    // 24KB; reused as transpose buffer post-loop
    __shared__ int   sh_hi;
    int tid    = threadIdx.x;
    int lane   = tid & 31;
    int warpid = tid >> 5;
    int pair   = warpid >> 1;            // node index within block (0..3)
    int half   = warpid & 1;             // which 4 rbf this warp owns
    int node0  = blockIdx.x * 4;         // 2500 blocks * 4 nodes = 10000
    int node   = node0 + pair;

    int s0  = g_start[node];
    int n_e = g_cnt[node];
    int s1  = s0 + n_e;

    int blk_lo = g_start[node0];
    if (warpid == 7 && lane == 0) sh_hi = s1;

    float accS[4], accD[4];
#pragma unroll
    for (int n = 0; n < 4; n++) { accS[n] = 0.0f; accD[n] = 0.0f; }

    __syncthreads();                     // sh_hi ready; all g_cnt reads done
    int blk_hi = sh_hi;
    if (half == 0 && lane == 0) g_cnt[node] = 0;   // restore zero state for next replay

    int qoff = 24 + 4 * half;            // this warp's 4 sines

    for (int lo = blk_lo; lo < blk_hi; lo += CAP) {
        int cnt = min(CAP, blk_hi - lo);
        const float4* src4 = reinterpret_cast<const float4*>(g_pay + (size_t)lo * 32);
        int n4 = cnt * 8;
        for (int i = tid; i < n4; i += 256)
            reinterpret_cast<float4*>(pay_sh)[i] = src4[i];
        __syncthreads();

        int a = max(s0, lo);
        int b = min(s1, lo + cnt);
#pragma unroll 2
        for (int t = a; t < b; t++) {
            const float* P = pay_sh + (t - lo) * 32;
            float  mA  = P[lane];                                // lanes 0..19 meaningful
            float4 q   = *reinterpret_cast<const float4*>(P + qoff);
            unsigned sgn = __float_as_uint(P[20]);
            float  mS  = __uint_as_float(__float_as_uint(mA) ^ sgn);

            accS[0] = fmaf(mA, q.x, accS[0]);  accD[0] = fmaf(mS, q.x, accD[0]);
            accS[1] = fmaf(mA, q.y, accS[1]);  accD[1] = fmaf(mS, q.y, accD[1]);
            accS[2] = fmaf(mA, q.z, accS[2]);  accD[2] = fmaf(mS, q.z, accD[2]);
            accS[3] = fmaf(mA, q.w, accS[3]);  accD[3] = fmaf(mS, q.w, accD[3]);
        }
        __syncthreads();   // chunk fully consumed before overwrite / transpose reuse
    }

    // Transpose through (reused) shared: node slice = pair*320, layout [z][r][a].
    // S0 = (S+D)/2, S1 = (S-D)/2
    float* swn = pay_sh + pair * 320;
    if (lane < 20) {
#pragma unroll
        for (int n = 0; n < 4; n++) {
            int r = half * 4 + n;
            swn[r * 20 + lane]       = 0.5f * (accS[n] + accD[n]);
            swn[160 + r * 20 + lane] = 0.5f * (accS[n] - accD[n]);
        }
    }
    __syncthreads();

    // Epilogue: warps 0..3 each handle one node (all 8 rbf via r = lane/4)
    if (warpid < 4) {
        int node_e = node0 + warpid;
        const float* sw = pay_sh + warpid * 320;

        int r = lane >> 2;
        int g = lane & 3;
        const float* p0 = sw + r * 20 + g * 5;
        const float* p1 = p0 + 160;

        float W00 = W[0], W01 = W[1], W02 = W[2];
        float W10 = W[3], W11 = W[4], W12 = W[5];

        float C[5][3];
#pragma unroll
        for (int k = 0; k < 5; k++) {
            float v0 = p0[k], v1 = p1[k];
            C[k][0] = fmaf(v0, W00, v1 * W10);
            C[k][1] = fmaf(v0, W01, v1 * W11);
            C[k][2] = fmaf(v0, W02, v1 * W12);
        }

        float D0[3] = {0, 0, 0}, D1[3] = {0, 0, 0}, D2[3] = {0, 0, 0}, D3[3] = {0, 0, 0};
        if (g == 0) {
#pragma unroll
            for (int i = 0; i < 3; i++) {
                D0[i] = C[0][i];
                D1[i] = C[1][i] * C[1][i] + C[2][i] * C[2][i] + C[3][i] * C[3][i];
                D2[i] = C[4][i] * C[4][i];
            }
        } else if (g == 1) {
#pragma unroll
            for (int i = 0; i < 3; i++)
                D2[i] = 2.0f * C[0][i] * C[0][i] + 2.0f * C[1][i] * C[1][i] + C[2][i] * C[2][i]
                      + 2.0f * C[3][i] * C[3][i] + C[4][i] * C[4][i];
        } else if (g == 2) {
#pragma unroll
            for (int i = 0; i < 3; i++)
                D3[i] = C[0][i] * C[0][i] + 3.0f * C[1][i] * C[1][i] + 3.0f * C[2][i] * C[2][i]
                      + 3.0f * C[3][i] * C[3][i] + 6.0f * C[4][i] * C[4][i];
        } else {
#pragma unroll
            for (int i = 0; i < 3; i++)
                D3[i] = 3.0f * C[0][i] * C[0][i] + C[1][i] * C[1][i] + 3.0f * C[2][i] * C[2][i]
                      + 3.0f * C[3][i] * C[3][i] + C[4][i] * C[4][i];
        }

#pragma unroll
        for (int msk = 1; msk <= 2; msk <<= 1) {
#pragma unroll
            for (int i = 0; i < 3; i++) {
                D0[i] += __shfl_xor_sync(0xffffffffu, D0[i], msk);
                D1[i] += __shfl_xor_sync(0xffffffffu, D1[i], msk);
                D2[i] += __shfl_xor_sync(0xffffffffu, D2[i], msk);
                D3[i] += __shfl_xor_sync(0xffffffffu, D3[i], msk);
            }
        }

        if (g == 0) {
            int   zn = an[node_e];
            float e0 = zn ? W10 : W00;
            float e1 = zn ? W11 : W01;
            float e2 = zn ? W12 : W02;
            float q0 = e0 * e0, q1 = e1 * e1, q2 = e2 * e2;

            float v[36];
            v[0] = D0[0] * e0;  v[1] = D0[0] * e1;  v[2] = D0[0] * e2;
            v[3] = D0[1] * e0;  v[4] = D0[1] * e1;  v[5] = D0[1] * e2;
            v[6] = D0[2] * e0;  v[7] = D0[2] * e1;  v[8] = D0[2] * e2;

            v[9]  = D1[0] * q0; v[10] = D1[0] * q1; v[11] = D1[0] * q2;
            v[12] = D1[1] * q0; v[13] = D1[1] * q1; v[14] = D1[1] * q2;
            v[15] = D1[2] * q0; v[16] = D1[2] * q1; v[17] = D1[2] * q2;

            v[18] = D2[0] * q0; v[19] = D2[0] * q1; v[20] = D2[0] * q2;
            v[21] = D2[1] * q0; v[22] = D2[1] * q1; v[23] = D2[1] * q2;
            v[24] = D2[2] * q0; v[25] = D2[2] * q1; v[26] = D2[2] * q2;

            v[27] = D3[0] * q0; v[28] = D3[0] * q1; v[29] = D3[0] * q2;
            v[30] = D3[1] * q0; v[31] = D3[1] * q1; v[32] = D3[1] * q2;
            v[33] = D3[2] * q0; v[34] = D3[2] * q1; v[35] = D3[2] * q2;

            float4* o = reinterpret_cast<float4*>(out + (size_t)(node_e * 8 + r) * 36);
#pragma unroll
            for (int k = 0; k < 9; k++)
                o[k] = make_float4(v[4 * k], v[4 * k + 1], v[4 * k + 2], v[4 * k + 3]);
        }
    }
}

extern "C" void kernel_launch(void* const* d_in, const int* in_sizes, int n_in,
                              void* d_out, int out_size) {
    const int*   an = (const int*)d_in[1];
    const int*   ei = (const int*)d_in[2];
    const float* el = (const float*)d_in[3];
    const float* ev = (const float*)d_in[4];
    const float* W  = (const float*)d_in[5];
    float* out = (float*)d_out;

    hist_kernel<<<(NE + 255) / 256, 256>>>(ei);
    scan_kernel<<<1, 1024>>>();
    scatter_kernel<<<(NE + 255) / 256, 256>>>(ei, an, el, ev);
    gather_kernel<<<2500, 256>>>(an, W, out);   // 4 nodes per block, 2 warps per node
}

// round 17
// speedup vs baseline: 1.4824x; 1.1714x over previous
#include <cuda_runtime.h>
#include <cuda_bf16.h>

#define NE 100000
#define NN 10000
#define PI_F 3.14159265358979323846f
#define SQRT_2_CUT 0.6030226891555273f
#define CAP 192                 // edges per smem chunk (192*128B = 24KB)

__device__ int g_cnt[NN];      // statically zero-init; gather re-zeroes after reading
__device__ int g_start[NN];
__device__ int g_cursor[NN];
// Payload per CSR slot: 32 floats (one 128B line):
// [0:20)=mon_a*sc, [20]=sign word, [21:24)=pad, [24:32)=sin(n*theta)
__device__ __align__(128) float g_pay[NE * 32];

__constant__ int   c_lvl[20]  = {0, 1,1,1, 2,2,2,2,2,2, 3,3,3,3,3,3,3,3,3,3};
__constant__ float c_pref[20] = {1.f, 1.f,1.f,1.f,
                                 1.f,2.f,2.f,1.f,2.f,1.f,
                                 1.f,3.f,3.f,3.f,6.f,3.f,1.f,3.f,3.f,1.f};

__global__ void __launch_bounds__(256) hist_kernel(const int* __restrict__ ei) {
    int e = blockIdx.x * blockDim.x + threadIdx.x;
    if (e < NE) atomicAdd(&g_cnt[ei[NE + e]], 1);
}

// Single block, 1024 threads, coalesced smem-staged scan
__global__ void __launch_bounds__(1024) scan_kernel() {
    __shared__ int sh[10240];
    __shared__ int wsum[32];
    int tid = threadIdx.x;

    for (int i = tid; i < 10240; i += 1024) sh[i] = (i < NN) ? g_cnt[i] : 0;
    __syncthreads();

    int base = tid * 10;
    int local[10];
    int sum = 0;
#pragma unroll
    for (int k = 0; k < 10; k++) { local[k] = sum; sum += sh[base + k]; }

    int lane = tid & 31, w = tid >> 5;
    int incl = sum;
#pragma unroll
    for (int d = 1; d < 32; d <<= 1) {
        int v = __shfl_up_sync(0xffffffffu, incl, d);
        if (lane >= d) incl += v;
    }
    if (lane == 31) wsum[w] = incl;
    __syncthreads();
    if (w == 0) {
        int v = wsum[lane];
        int inc2 = v;
#pragma unroll
        for (int d = 1; d < 32; d <<= 1) {
            int t2 = __shfl_up_sync(0xffffffffu, inc2, d);
            if (lane >= d) inc2 += t2;
        }
        wsum[lane] = inc2 - v;
    }
    __syncthreads();

    int excl = incl - sum + wsum[w];
#pragma unroll
    for (int k = 0; k < 10; k++) sh[base + k] = excl + local[k];
    __syncthreads();

    for (int i = tid; i < NN; i += 1024) {
        int v = sh[i];
        g_start[i]  = v;
        g_cursor[i] = v;
    }
}

// scatter: per-edge math, payload written directly into CSR slot (one 128B line)
__global__ void __launch_bounds__(256) scatter_kernel(const int* __restrict__ ei,
                                                      const int* __restrict__ an,
                                                      const float* __restrict__ el,
                                                      const float* __restrict__ ev) {
    int e = blockIdx.x * blockDim.x + threadIdx.x;
    if (e >= NE) return;

    int src = ei[e];
    int dst = ei[NE + e];
    int z   = an[src];
    float r  = el[e];
    float vx = ev[3 * e + 0];
    float vy = ev[3 * e + 1];
    float vz = ev[3 * e + 2];

    float inv = rsqrtf(vx * vx + vy * vy + vz * vz);
    float x = vx * inv, y = vy * inv, zc = vz * inv;

    float u  = r * (1.0f / 5.5f);
    float u2 = u * u;
    float u6 = u2 * u2 * u2;
    float fc = 1.0f - 28.0f * u6 + 48.0f * u6 * u - 21.0f * u6 * u2;
    fc = (u < 1.0f) ? fc : 0.0f;

    float s, c;
    sincosf(PI_F * u, &s, &c);
    float sc   = SQRT_2_CUT / r * fc;          // positive
    float twoc = 2.0f * c;

    // monomials * sc
    float a0 = sc;
    float a1 = x * sc,  a2 = y * sc,  a3 = zc * sc;
    float a4 = x * a1,  a5 = y * a1,  a6 = zc * a1;
    float a7 = y * a2,  a8 = zc * a2, a9 = zc * a3;
    float a10 = x * a4, a11 = y * a4, a12 = zc * a4;
    float a13 = y * a5, a14 = zc * a5, a15 = zc * a6;
    float a16 = y * a7, a17 = zc * a7, a18 = zc * a8, a19 = zc * a9;

    // sin(n*theta), n=1..8 via Chebyshev
    float s1 = s;
    float s2 = twoc * s1;
    float s3 = fmaf(twoc, s2, -s1);
    float s4 = fmaf(twoc, s3, -s2);
    float s5 = fmaf(twoc, s4, -s3);
    float s6 = fmaf(twoc, s5, -s4);
    float s7 = fmaf(twoc, s6, -s5);
    float s8 = fmaf(twoc, s7, -s6);

    float sgn = __uint_as_float(z ? 0x80000000u : 0u);

    int pos = atomicAdd(&g_cursor[dst], 1);
    float4* P = reinterpret_cast<float4*>(g_pay + (size_t)pos * 32);
    P[0] = make_float4(a0,  a1,  a2,  a3);
    P[1] = make_float4(a4,  a5,  a6,  a7);
    P[2] = make_float4(a8,  a9,  a10, a11);
    P[3] = make_float4(a12, a13, a14, a15);
    P[4] = make_float4(a16, a17, a18, a19);
    P[5] = make_float4(sgn, 0.0f, 0.0f, 0.0f);
    P[6] = make_float4(s1, s2, s3, s4);
    P[7] = make_float4(s5, s6, s7, s8);
}

// 8 warps = 8 consecutive nodes; smem-staged chunks; thread-parallel in-block
// epilogue (one thread per (node, rbf)); coalesced output copy.
#define SD_STRIDE 325                       // node slice stride (bank-conflict-free)
#define OUT_BASE  2600                      // float offset of output staging
#define OUT_PAD   37                        // padded stride of 36-float tiles
__global__ void __launch_bounds__(256) gather_kernel(const int* __restrict__ an,
                                                     const float* __restrict__ W,
                                                     float* __restrict__ out) {
    __shared__ float pay_sh[CAP * 32];      // 24KB; reused: SD at [0,2600), out at [2600,4968)
    __shared__ int   sh_hi;
    int tid    = threadIdx.x;
    int lane   = tid & 31;
    int warpid = tid >> 5;
    int node0  = blockIdx.x * 8;            // 1250 blocks * 8 = 10000
    int node   = node0 + warpid;

    int s0  = g_start[node];
    int n_e = g_cnt[node];
    if (lane == 0) g_cnt[node] = 0;         // restore zero state for next replay
    int s1  = s0 + n_e;

    int blk_lo = g_start[node0];
    if (warpid == 7 && lane == 0) sh_hi = s1;

    float accS[8], accD[8];
#pragma unroll
    for (int n = 0; n < 8; n++) { accS[n] = 0.0f; accD[n] = 0.0f; }

    __syncthreads();
    int blk_hi = sh_hi;

    for (int lo = blk_lo; lo < blk_hi; lo += CAP) {
        int cnt = min(CAP, blk_hi - lo);
        const float4* src4 = reinterpret_cast<const float4*>(g_pay + (size_t)lo * 32);
        int n4 = cnt * 8;
        for (int i = tid; i < n4; i += 256)
            reinterpret_cast<float4*>(pay_sh)[i] = src4[i];
        __syncthreads();

        int a = max(s0, lo);
        int b = min(s1, lo + cnt);
#pragma unroll 4
        for (int t = a; t < b; t++) {
            const float* P = pay_sh + (t - lo) * 32;
            float  mA  = P[lane];                                // lanes 0..19 meaningful
            float4 qa  = *reinterpret_cast<const float4*>(P + 24);
            float4 qb  = *reinterpret_cast<const float4*>(P + 28);
            unsigned sgn = __float_as_uint(P[20]);
            float  mS  = __uint_as_float(__float_as_uint(mA) ^ sgn);

            accS[0] = fmaf(mA, qa.x, accS[0]);  accD[0] = fmaf(mS, qa.x, accD[0]);
            accS[1] = fmaf(mA, qa.y, accS[1]);  accD[1] = fmaf(mS, qa.y, accD[1]);
            accS[2] = fmaf(mA, qa.z, accS[2]);  accD[2] = fmaf(mS, qa.z, accD[2]);
            accS[3] = fmaf(mA, qa.w, accS[3]);  accD[3] = fmaf(mS, qa.w, accD[3]);
            accS[4] = fmaf(mA, qb.x, accS[4]);  accD[4] = fmaf(mS, qb.x, accD[4]);
            accS[5] = fmaf(mA, qb.y, accS[5]);  accD[5] = fmaf(mS, qb.y, accD[5]);
            accS[6] = fmaf(mA, qb.z, accS[6]);  accD[6] = fmaf(mS, qb.z, accD[6]);
            accS[7] = fmaf(mA, qb.w, accS[7]);  accD[7] = fmaf(mS, qb.w, accD[7]);
        }
        __syncthreads();
    }

    // Transpose into smem: node slice stride 325, layout [r][a] with S1 at +160.
    // S0 = (S+D)/2, S1 = (S-D)/2
    {
        float* swn = pay_sh + warpid * SD_STRIDE;
        if (lane < 20) {
#pragma unroll
            for (int n = 0; n < 8; n++) {
                swn[n * 20 + lane]       = 0.5f * (accS[n] + accD[n]);
                swn[160 + n * 20 + lane] = 0.5f * (accS[n] - accD[n]);
            }
        }
    }
    __syncthreads();

    // Thread-parallel epilogue: one thread per (node, rbf) = 64 threads.
    if (tid < 64) {
        int nl = tid >> 3;                  // local node 0..7
        int r  = tid & 7;

        float W00 = W[0], W01 = W[1], W02 = W[2];
        float W10 = W[3], W11 = W[4], W12 = W[5];

        const float* p0 = pay_sh + nl * SD_STRIDE + r * 20;
        const float* p1 = p0 + 160;

        float D0[3] = {0, 0, 0}, DL[3][3] = {{0,0,0},{0,0,0},{0,0,0}};
#pragma unroll
        for (int a = 0; a < 20; a++) {
            float v0 = p0[a];
            float v1 = p1[a];
            float C0 = fmaf(v0, W00, v1 * W10);
            float C1 = fmaf(v0, W01, v1 * W11);
            float C2 = fmaf(v0, W02, v1 * W12);
            if (a == 0) {
                D0[0] = C0; D0[1] = C1; D0[2] = C2;
            } else {
                int   l = c_lvl[a] - 1;
                float p = c_pref[a];
                DL[l][0] = fmaf(p * C0, C0, DL[l][0]);
                DL[l][1] = fmaf(p * C1, C1, DL[l][1]);
                DL[l][2] = fmaf(p * C2, C2, DL[l][2]);
            }
        }

        int   zn = an[node0 + nl];
        float e0 = zn ? W10 : W00;
        float e1 = zn ? W11 : W01;
        float e2 = zn ? W12 : W02;
        float q0 = e0 * e0, q1 = e1 * e1, q2 = e2 * e2;

        float* o = pay_sh + OUT_BASE + tid * OUT_PAD;
        o[0] = D0[0] * e0;  o[1] = D0[0] * e1;  o[2] = D0[0] * e2;
        o[3] = D0[1] * e0;  o[4] = D0[1] * e1;  o[5] = D0[1] * e2;
        o[6] = D0[2] * e0;  o[7] = D0[2] * e1;  o[8] = D0[2] * e2;
#pragma unroll
        for (int l = 0; l < 3; l++) {
            float* of = o + 9 + l * 9;
            of[0] = DL[l][0] * q0;  of[1] = DL[l][0] * q1;  of[2] = DL[l][0] * q2;
            of[3] = DL[l][1] * q0;  of[4] = DL[l][1] * q1;  of[5] = DL[l][1] * q2;
            of[6] = DL[l][2] * q0;  of[7] = DL[l][2] * q1;  of[8] = DL[l][2] * q2;
        }
    }
    __syncthreads();

    // Coalesced output copy: block tile = 8 nodes * 8 rbf * 36 = 2304 contiguous floats.
    {
        float* ob = out + (size_t)blockIdx.x * 2304;
        for (int j = tid; j < 2304; j += 256) {
            int ti = j / 36;
            int k  = j - ti * 36;
            ob[j] = pay_sh[OUT_BASE + ti * OUT_PAD + k];
        }
    }
}

extern "C" void kernel_launch(void* const* d_in, const int* in_sizes, int n_in,
                              void* d_out, int out_size) {
    const int*   an = (const int*)d_in[1];
    const int*   ei = (const int*)d_in[2];
    const float* el = (const float*)d_in[3];
    const float* ev = (const float*)d_in[4];
    const float* W  = (const float*)d_in[5];
    float* out = (float*)d_out;

    hist_kernel<<<(NE + 255) / 256, 256>>>(ei);
    scan_kernel<<<1, 1024>>>();
    scatter_kernel<<<(NE + 255) / 256, 256>>>(ei, an, el, ev);
    gather_kernel<<<1250, 256>>>(an, W, out);   // 8 nodes per block
}